// round 6
// baseline (speedup 1.0000x reference)
#include <cuda_runtime.h>
#include <cstdint>

#define Bn 256
#define Tn 512
#define Hn 256
#define G3 768

#define NBG 8          // batch groups (32 rows each)
#define NCG 16         // column groups (16 h-cols each)
#define RNN_BLOCKS (NBG * NCG)      // 128
#define RNN_THREADS 256
#define HS_LD 40       // padded hs row stride (floats)

// ---------------- scratch (device globals: no allocation allowed) ----------
__device__ float g_Gi[(size_t)Tn * G3 * Bn];   // [t][g][b], g = gate*256 + c
__device__ float g_h[2 * Hn * Bn];             // ping-pong, [p][c][b]
__device__ unsigned char g_rst[Tn * Bn];       // [t][b], normalized 0/1
__device__ unsigned g_cnt2[NBG * 16];          // per-bg barrier counters (64B apart)
__device__ unsigned g_gen2[NBG * 16];

// ---------------- packed fp32 FMA (Blackwell f32x2) -------------------------
__device__ __forceinline__ float2 ffma2(float2 a, float2 b, float2 c) {
    unsigned long long au = *reinterpret_cast<unsigned long long*>(&a);
    unsigned long long bu = *reinterpret_cast<unsigned long long*>(&b);
    unsigned long long cu = *reinterpret_cast<unsigned long long*>(&c);
    unsigned long long du;
    asm("fma.rn.f32x2 %0, %1, %2, %3;" : "=l"(du) : "l"(au), "l"(bu), "l"(cu));
    return *reinterpret_cast<float2*>(&du);
}
__device__ __forceinline__ float2 add2(float2 a, float2 b) {
    return make_float2(a.x + b.x, a.y + b.y);
}

// ---------------- init ------------------------------------------------------
__global__ void init_kernel(const float* __restrict__ h0,
                            const unsigned char* __restrict__ resets) {
    int i = blockIdx.x * blockDim.x + threadIdx.x;
    if (i < NBG) { g_cnt2[i * 16] = 0; g_gen2[i * 16] = 0; }

    // resets dtype ambiguous (int32 vs bool/u8): int32 0/1 LE has zero bytes
    // at offsets i%4 != 0.
    bool is_u8 = false;
    #pragma unroll 4
    for (int j = 0; j < 64; j++) {
        if (resets[j * 4 + 1] | resets[j * 4 + 2] | resets[j * 4 + 3]) is_u8 = true;
    }

    if (i < Hn * Bn) {
        int c = i / Bn, b = i % Bn;
        g_h[c * Bn + b] = h0[b * Hn + c];   // [c][b] <- [b][c]
    }
    if (i < Tn * Bn) {
        int t = i / Bn, b = i % Bn;
        int src = b * Tn + t;
        unsigned char v;
        if (is_u8) v = resets[src] ? 1 : 0;
        else       v = reinterpret_cast<const int*>(resets)[src] ? 1 : 0;
        g_rst[i] = v;
    }
}

// ---------------- Gi = x @ Wi + bi, stored [t][g][b] ------------------------
// 64(g) x 128(b) tile, 256 threads, 4g x 8b micro-tile, FFMA2 inner loop.
// (unchanged from R4-passing version)
#define BS_LD 132

__global__ void __launch_bounds__(256) gi_gemm(const float* __restrict__ x,
                                               const float* __restrict__ Wi,
                                               const float* __restrict__ bi) {
    int t  = blockIdx.z;
    int g0 = blockIdx.y * 64;
    int b0 = blockIdx.x * 128;

    __shared__ float As[16][64];
    __shared__ float Bs[16 * BS_LD];

    int tid = threadIdx.x;
    int tx = tid & 15;
    int ty = tid >> 4;

    float2 acc[4][4];
    #pragma unroll
    for (int i = 0; i < 4; i++)
        #pragma unroll
        for (int j = 0; j < 4; j++) acc[i][j] = make_float2(0.f, 0.f);

    for (int k0 = 0; k0 < Hn; k0 += 16) {
        {
            int gg = tid & 63;
            int kk = tid >> 6;
            #pragma unroll
            for (int r = 0; r < 4; r++)
                As[kk + 4 * r][gg] = Wi[(size_t)(k0 + kk + 4 * r) * G3 + g0 + gg];
        }
        {
            #pragma unroll
            for (int rep = 0; rep < 2; rep++) {
                int idx = tid + rep * 256;
                int bb = idx >> 2;
                int kq = (idx & 3) * 4;
                const float4 v = *reinterpret_cast<const float4*>(
                    &x[((size_t)(b0 + bb) * Tn + t) * Hn + k0 + kq]);
                Bs[(kq + 0) * BS_LD + bb] = v.x;
                Bs[(kq + 1) * BS_LD + bb] = v.y;
                Bs[(kq + 2) * BS_LD + bb] = v.z;
                Bs[(kq + 3) * BS_LD + bb] = v.w;
            }
        }
        __syncthreads();

        #pragma unroll
        for (int kk = 0; kk < 16; kk++) {
            float4 a4 = *reinterpret_cast<const float4*>(&As[kk][ty * 4]);
            float4 bA = *reinterpret_cast<const float4*>(&Bs[kk * BS_LD + tx * 8]);
            float4 bB = *reinterpret_cast<const float4*>(&Bs[kk * BS_LD + tx * 8 + 4]);
            float2 bp[4] = { make_float2(bA.x, bA.y), make_float2(bA.z, bA.w),
                             make_float2(bB.x, bB.y), make_float2(bB.z, bB.w) };
            float av[4] = { a4.x, a4.y, a4.z, a4.w };
            #pragma unroll
            for (int i = 0; i < 4; i++) {
                float2 ai = make_float2(av[i], av[i]);
                #pragma unroll
                for (int j = 0; j < 4; j++)
                    acc[i][j] = ffma2(ai, bp[j], acc[i][j]);
            }
        }
        __syncthreads();
    }

    #pragma unroll
    for (int i = 0; i < 4; i++) {
        int g = g0 + ty * 4 + i;
        float bv = bi[g];
        float4 o0 = make_float4(acc[i][0].x + bv, acc[i][0].y + bv,
                                acc[i][1].x + bv, acc[i][1].y + bv);
        float4 o1 = make_float4(acc[i][2].x + bv, acc[i][2].y + bv,
                                acc[i][3].x + bv, acc[i][3].y + bv);
        float* dst = &g_Gi[((size_t)t * G3 + g) * Bn + b0 + tx * 8];
        *reinterpret_cast<float4*>(dst)     = o0;
        *reinterpret_cast<float4*>(dst + 4) = o1;
    }
}

// ---------------- recurrent scan -------------------------------------------
// Block (bg,cg): batch rows [bg*32, +32), h-cols [cg*16, +16).
// 256 threads: tid = kh*128 + bq*16 + cl.
//   kh: k-half (0,1); bq: 0..7 -> 4 batch rows each; cl: 0..15 -> 1 col.
// Each thread: partial gh for 4 rows over its k-half; after exchange it
// activates 2 rows (kh selects which pair).
__device__ __forceinline__ float sigmoidf_(float v) {
    return __fdividef(1.f, 1.f + __expf(-v));
}

__global__ void __launch_bounds__(RNN_THREADS, 1)
rnn_kernel(const float* __restrict__ Wh, const float* __restrict__ bnb,
           float* __restrict__ out) {
    extern __shared__ char smraw[];
    float4* ws  = reinterpret_cast<float4*>(smraw);                  // [256][16] 64KB
    float*  hs  = reinterpret_cast<float*>(smraw + 65536);           // [256][HS_LD] 40KB
    float2* red = reinterpret_cast<float2*>(smraw + 65536 + Hn * HS_LD * 4); // [128][2][3]

    const int tid = threadIdx.x;
    const int bg  = blockIdx.x >> 4;
    const int cg  = blockIdx.x & 15;
    const int kh  = tid >> 7;            // 0,1
    const int bq  = (tid >> 4) & 7;      // 0..7
    const int cl  = tid & 15;            // 0..15
    const int cG  = cg * 16 + cl;
    const int bB  = bg * 32;

    // ---- load Wh slice into SMEM, packed {wr, wz, wn, 0} per (k, cl) ----
    for (int idx = tid; idx < Hn * 16; idx += RNN_THREADS) {
        int k = idx >> 4, c = cg * 16 + (idx & 15);
        const float* w = Wh + (size_t)k * G3;
        ws[idx] = make_float4(w[c], w[256 + c], w[512 + c], 0.f);
    }
    const float bnv = bnb[cG];
    __syncthreads();

    float* outy = out + Hn * Bn;              // ys after hT
    const int rown = bq * 4 + kh * 2;         // first of 2 rows this thread activates
    const int b0g  = bB + rown;

    unsigned* cntp = &g_cnt2[bg * 16];
    unsigned* genp = &g_gen2[bg * 16];

    for (int t = 0; t < Tn; t++) {
        const int p = t & 1;
        const float* hin = g_h + p * (Hn * Bn);

        // ---- stage masked h[32b, 256k] into hs (L2 reads, .cg) ----
        #pragma unroll
        for (int it = 0; it < 8; it++) {
            int fidx = it * RNN_THREADS + tid;   // 0..2047 float4s
            int row  = fidx >> 3;                // k index
            int c4   = (fidx & 7) * 4;           // batch offset
            float4 v = __ldcg(reinterpret_cast<const float4*>(
                &hin[row * Bn + bB + c4]));
            uchar4 q = *reinterpret_cast<const uchar4*>(&g_rst[t * Bn + bB + c4]);
            v.x = q.x ? 0.f : v.x;
            v.y = q.y ? 0.f : v.y;
            v.z = q.z ? 0.f : v.z;
            v.w = q.w ? 0.f : v.w;
            *reinterpret_cast<float4*>(&hs[row * HS_LD + c4]) = v;
        }

        // ---- prefetch gi for the 2 rows this thread activates ----
        const float* gi = g_Gi + (size_t)t * G3 * Bn;
        float2 gr = __ldcs(reinterpret_cast<const float2*>(&gi[(      cG) * Bn + b0g]));
        float2 gz = __ldcs(reinterpret_cast<const float2*>(&gi[(256 + cG) * Bn + b0g]));
        float2 gn = __ldcs(reinterpret_cast<const float2*>(&gi[(512 + cG) * Bn + b0g]));

        __syncthreads();

        // ---- k-loop over this thread's half: partials for 4 rows ----
        float2 ar0 = {0,0}, ar1 = {0,0};
        float2 az0 = {0,0}, az1 = {0,0};
        float2 an0 = {0,0}, an1 = {0,0};
        {
            const float4* wp = ws + cl;
            const float*  hp = hs + bq * 4;
            const int kb = kh * 128;
            #pragma unroll 8
            for (int k = 0; k < 128; k++) {
                const int kk = kb + k;
                float4 w  = wp[kk * 16];
                float4 h4 = *reinterpret_cast<const float4*>(&hp[kk * HS_LD]);
                float2 h01 = make_float2(h4.x, h4.y);
                float2 h23 = make_float2(h4.z, h4.w);
                float2 wr = make_float2(w.x, w.x);
                float2 wz = make_float2(w.y, w.y);
                float2 wn = make_float2(w.z, w.z);
                ar0 = ffma2(wr, h01, ar0); ar1 = ffma2(wr, h23, ar1);
                az0 = ffma2(wz, h01, az0); az1 = ffma2(wz, h23, az1);
                an0 = ffma2(wn, h01, an0); an1 = ffma2(wn, h23, an1);
            }
        }

        // ---- exchange partner-half partials through SMEM ----
        // kh==0 activates rows {0,1} of its quad, sends pair {2,3}; kh==1 mirror.
        {
            float2* slot = red + ((bq * 16 + cl) * 2 + kh) * 3;
            if (kh == 0) { slot[0] = ar1; slot[1] = az1; slot[2] = an1; }
            else         { slot[0] = ar0; slot[1] = az0; slot[2] = an0; }
        }
        __syncthreads();
        float2 sr, sz, sn;
        {
            const float2* ps = red + ((bq * 16 + cl) * 2 + (1 - kh)) * 3;
            if (kh == 0) { sr = add2(ar0, ps[0]); sz = add2(az0, ps[1]); sn = add2(an0, ps[2]); }
            else         { sr = add2(ar1, ps[0]); sz = add2(az1, ps[1]); sn = add2(an1, ps[2]); }
        }

        // ---- activation + h' for 2 rows ----
        float2 hprev = *reinterpret_cast<const float2*>(&hs[cG * HS_LD + rown]);
        float r0 = sigmoidf_(gr.x + sr.x);
        float z0 = sigmoidf_(gz.x + sz.x);
        float n0 = tanhf(gn.x + r0 * (sn.x + bnv));
        float nh0 = (1.f - z0) * n0 + z0 * hprev.x;
        float r1 = sigmoidf_(gr.y + sr.y);
        float z1 = sigmoidf_(gz.y + sz.y);
        float n1 = tanhf(gn.y + r1 * (sn.y + bnv));
        float nh1 = (1.f - z1) * n1 + z1 * hprev.y;

        float* hout = g_h + (p ^ 1) * (Hn * Bn);
        __stcg(reinterpret_cast<float2*>(&hout[cG * Bn + b0g]),
               make_float2(nh0, nh1));

        outy[((size_t)(b0g    ) * Tn + t) * Hn + cG] = nh0;
        outy[((size_t)(b0g + 1) * Tn + t) * Hn + cG] = nh1;
        if (t == Tn - 1) {
            out[(b0g    ) * Hn + cG] = nh0;
            out[(b0g + 1) * Hn + cG] = nh1;
        }

        // ---- barrier among the 16 blocks of this batch-group ----
        if (t < Tn - 1) {
            __syncthreads();
            if (tid == 0) {
                unsigned a;
                asm volatile("atom.acq_rel.gpu.add.u32 %0, [%1], 1;"
                             : "=r"(a) : "l"(cntp) : "memory");
                if (a == 15u) {
                    asm volatile("st.relaxed.gpu.u32 [%0], 0;"
                                 :: "l"(cntp) : "memory");
                    asm volatile("red.release.gpu.add.u32 [%0], 1;"
                                 :: "l"(genp) : "memory");
                } else {
                    unsigned target = (unsigned)(t + 1), gv;
                    do {
                        asm volatile("ld.acquire.gpu.u32 %0, [%1];"
                                     : "=r"(gv) : "l"(genp) : "memory");
                    } while (gv < target);
                }
            }
            __syncthreads();
        }
    }
}

// ---------------- launch ----------------------------------------------------
#define RNN_SMEM (65536 + Hn * HS_LD * 4 + 128 * 2 * 3 * 8)

extern "C" void kernel_launch(void* const* d_in, const int* in_sizes, int n_in,
                              void* d_out, int out_size) {
    const float*         x      = (const float*)d_in[0];
    const unsigned char* resets = (const unsigned char*)d_in[1];
    const float*         Wi     = (const float*)d_in[2];
    const float*         bi     = (const float*)d_in[3];
    const float*         Wh     = (const float*)d_in[4];
    const float*         bn     = (const float*)d_in[5];
    const float*         h0     = (const float*)d_in[6];
    float* out = (float*)d_out;

    cudaFuncSetAttribute(rnn_kernel, cudaFuncAttributeMaxDynamicSharedMemorySize,
                         RNN_SMEM);

    init_kernel<<<(Tn * Bn + 255) / 256, 256>>>(h0, resets);

    dim3 g(Bn / 128, G3 / 64, Tn);
    gi_gemm<<<g, 256>>>(x, Wi, bi);

    rnn_kernel<<<RNN_BLOCKS, RNN_THREADS, RNN_SMEM>>>(Wh, bn, out);
}